// round 11
// baseline (speedup 1.0000x reference)
#include <cuda_runtime.h>

// Problem dims (compile-time, from reference)
#define BDIM 2
#define CDIM 3
#define DDIM 128
#define HDIM 192
#define WDIM 192

// ---------------------------------------------------------------------------
// Fused X+Y kernel: one 192-thread block per (b,c,d) slice (768 blocks).
// Phase X: proven warp-transpose solve along W (6 warps x 32 rows), result
//          written to out (L2-hot).
// Phase Y: proven register-hold solve along H (thread t = column w),
//          HOLD=96 in regs, first 96 y-steps spilled in-place to out (L2).
// Y reads the X result straight from L2 -> saves a full DRAM volume.
// ---------------------------------------------------------------------------
constexpr int FWARPS = 6;
constexpr int FTPB   = FWARPS * 32;     // 192
constexpr int YHOLD  = 96;
constexpr int YSPILL = HDIM - YHOLD;    // 96

__global__ __launch_bounds__(FTPB) void fused_xy_kernel(
    const float* __restrict__ in, float* __restrict__ out,
    const float* __restrict__ ax, const float* __restrict__ bx,
    const float* __restrict__ cx,
    const float* __restrict__ ay, const float* __restrict__ by,
    const float* __restrict__ cy)
{
    __shared__ float tile[FWARPS][32][33];
    __shared__ float x_inva[WDIM], x_b[WDIM], x_c[WDIM];
    __shared__ float y_inva[HDIM], y_binva[HDIM], y_c[HDIM];

    const int t    = threadIdx.x;
    const int wid  = t >> 5;
    const int lane = t & 31;

    for (int i = t; i < WDIM; i += FTPB) {
        x_inva[i] = 1.0f / ax[i];
        x_b[i] = (i < WDIM - 1) ? bx[i] : 0.0f;
        x_c[i] = (i < WDIM - 1) ? cx[i] : 0.0f;
        const float ivy = 1.0f / ay[i];
        y_inva[i]  = ivy;
        y_binva[i] = (i < HDIM - 1) ? by[i] * ivy : 0.0f;
        y_c[i]     = (i < HDIM - 1) ? cy[i] : 0.0f;
    }
    __syncthreads();

    const size_t sbase = (size_t)blockIdx.x * (HDIM * WDIM);

    // ================= Phase X (proven warp-transpose solve) ===============
    {
        float (*tl)[33] = tile[wid];
        const float* inw  = in  + sbase + (size_t)wid * 32 * WDIM;
        float*       outw = out + sbase + (size_t)wid * 32 * WDIM;
        const int r0 = lane >> 3;
        const int cm = (lane & 7) * 4;

        float carry = 0.0f;
        float yreg[32];

        // forward sweep
        for (int k = 0; k < 6; k++) {
            const int c0 = k * 32;
            #pragma unroll
            for (int rr = 0; rr < 32; rr += 4) {
                const int r = rr + r0;
                float4 v = *(const float4*)(inw + (size_t)r * WDIM + c0 + cm);
                tl[r][cm]     = v.x; tl[r][cm + 1] = v.y;
                tl[r][cm + 2] = v.z; tl[r][cm + 3] = v.w;
            }
            __syncwarp();
            #pragma unroll
            for (int j = 0; j < 32; j++) {
                const float x = tl[lane][j];
                const int i = c0 + j;
                carry = (i == 0) ? x : fmaf(-x_c[i - 1], carry, x);
                yreg[j] = carry;
            }
            if (k < 5) {
                #pragma unroll
                for (int j = 0; j < 32; j++) tl[lane][j] = yreg[j];
                __syncwarp();
                #pragma unroll
                for (int rr = 0; rr < 32; rr += 4) {
                    const int r = rr + r0;
                    float4 v = make_float4(tl[r][cm], tl[r][cm + 1],
                                           tl[r][cm + 2], tl[r][cm + 3]);
                    *(float4*)(outw + (size_t)r * WDIM + c0 + cm) = v;
                }
            }
            __syncwarp();
        }

        // backward sweep: chunk 5 from registers
        {
            const int c0 = 5 * 32;
            #pragma unroll
            for (int j = 31; j >= 0; j--) {
                const int i = c0 + j;
                const float x = yreg[j];
                carry = (i == WDIM - 1) ? x * x_inva[i]
                                        : fmaf(-x_b[i], carry, x) * x_inva[i];
                yreg[j] = carry;
            }
            #pragma unroll
            for (int j = 0; j < 32; j++) tl[lane][j] = yreg[j];
            __syncwarp();
            #pragma unroll
            for (int rr = 0; rr < 32; rr += 4) {
                const int r = rr + r0;
                float4 v = make_float4(tl[r][cm], tl[r][cm + 1],
                                       tl[r][cm + 2], tl[r][cm + 3]);
                *(float4*)(outw + (size_t)r * WDIM + c0 + cm) = v;
            }
            __syncwarp();
        }
        for (int k = 4; k >= 0; k--) {
            const int c0 = k * 32;
            #pragma unroll
            for (int rr = 0; rr < 32; rr += 4) {
                const int r = rr + r0;
                float4 v = *(const float4*)(outw + (size_t)r * WDIM + c0 + cm);
                tl[r][cm]     = v.x; tl[r][cm + 1] = v.y;
                tl[r][cm + 2] = v.z; tl[r][cm + 3] = v.w;
            }
            __syncwarp();
            #pragma unroll
            for (int j = 31; j >= 0; j--) {
                const int i = c0 + j;
                carry = fmaf(-x_b[i], carry, tl[lane][j]) * x_inva[i];
                yreg[j] = carry;
            }
            #pragma unroll
            for (int j = 0; j < 32; j++) tl[lane][j] = yreg[j];
            __syncwarp();
            #pragma unroll
            for (int rr = 0; rr < 32; rr += 4) {
                const int r = rr + r0;
                float4 v = make_float4(tl[r][cm], tl[r][cm + 1],
                                       tl[r][cm + 2], tl[r][cm + 3]);
                *(float4*)(outw + (size_t)r * WDIM + c0 + cm) = v;
            }
            __syncwarp();
        }
    }

    __syncthreads();   // X result for the whole slice visible

    // ================= Phase Y (R8 register-hold solve) ====================
    {
        float* p = out + sbase + t;     // column w = t, stride WDIM over h

        float yreg[YHOLD];
        float carry = p[0];
        p[0] = carry;
        #pragma unroll
        for (int i = 1; i < HDIM; i++) {
            carry = fmaf(-y_c[i - 1], carry, p[(size_t)i * WDIM]);
            if (i < YSPILL) p[(size_t)i * WDIM] = carry;
            else            yreg[i - YSPILL] = carry;
        }

        carry = 0.0f;
        #pragma unroll
        for (int i = HDIM - 1; i >= YSPILL; i--) {
            carry = fmaf(-y_binva[i], carry, yreg[i - YSPILL] * y_inva[i]);
            p[(size_t)i * WDIM] = carry;
        }
        #pragma unroll
        for (int i = YSPILL - 1; i >= 0; i--) {
            carry = fmaf(-y_binva[i], carry, p[(size_t)i * WDIM] * y_inva[i]);
            p[(size_t)i * WDIM] = carry;
        }
    }
}

// ---------------------------------------------------------------------------
// Z pass (R8 measured-best, unchanged): scalar thread-per-line, y fully
// register-held (N=128), 128-thread blocks.
// ---------------------------------------------------------------------------
constexpr int STPB = 128;

__global__ __launch_bounds__(STPB, 1) void solve_z_kernel(
    float* __restrict__ data,
    const float* __restrict__ a, const float* __restrict__ b,
    const float* __restrict__ c)
{
    __shared__ float s_inva[DDIM], s_binva[DDIM], s_c[DDIM];
    const int t = threadIdx.x;
    for (int i = t; i < DDIM; i += STPB) {
        const float iv = 1.0f / a[i];
        s_inva[i]  = iv;
        s_binva[i] = (i < DDIM - 1) ? b[i] * iv : 0.0f;
        s_c[i]     = (i < DDIM - 1) ? c[i] : 0.0f;
    }
    __syncthreads();

    constexpr int PL = HDIM * WDIM;
    const int L  = blockIdx.x * STPB + t;     // line over (b,c) x (h,w)
    const int bc = L / PL;
    const int hw = L - bc * PL;
    float* p = data + (size_t)bc * (DDIM * PL) + hw;

    float yreg[DDIM];
    float carry = p[0];
    yreg[0] = carry;
    #pragma unroll
    for (int i = 1; i < DDIM; i++) {
        carry = fmaf(-s_c[i - 1], carry, p[(size_t)i * PL]);
        yreg[i] = carry;
    }

    carry = 0.0f;
    #pragma unroll
    for (int i = DDIM - 1; i >= 0; i--) {
        carry = fmaf(-s_binva[i], carry, yreg[i] * s_inva[i]);
        p[(size_t)i * PL] = carry;
    }
}

// ---------------------------------------------------------------------------
// Launch
// ---------------------------------------------------------------------------
extern "C" void kernel_launch(void* const* d_in, const int* in_sizes, int n_in,
                              void* d_out, int out_size)
{
    const float* field = (const float*)d_in[0];
    const float* ax = (const float*)d_in[1];
    const float* bx = (const float*)d_in[2];
    const float* cx = (const float*)d_in[3];
    const float* ay = (const float*)d_in[4];
    const float* by = (const float*)d_in[5];
    const float* cy = (const float*)d_in[6];
    const float* az = (const float*)d_in[7];
    const float* bz = (const float*)d_in[8];
    const float* cz = (const float*)d_in[9];
    float* out = (float*)d_out;

    (void)in_sizes; (void)n_in; (void)out_size;

    // Fused X+Y: one block per (b,c,d) slice = 2*3*128 = 768 blocks
    fused_xy_kernel<<<BDIM * CDIM * DDIM, FTPB>>>(
        field, out, ax, bx, cx, ay, by, cy);

    // Z: lines = b*c*h*w = 221184 / 128 = 1728 blocks
    const int lines_z = BDIM * CDIM * HDIM * WDIM;
    solve_z_kernel<<<lines_z / STPB, STPB>>>(out, az, bz, cz);
}